// round 3
// baseline (speedup 1.0000x reference)
#include <cuda_runtime.h>
#include <cstdint>

// Problem-size constants (match the reference; runtime values derived from
// in_sizes must not exceed these static capacities).
#define NMAX 100000
#define EMAX 1600000
#define ETOT (EMAX + NMAX)
#define SCAN_CHUNK 1024
#define NBMAX ((NMAX + SCAN_CHUNK - 1) / SCAN_CHUNK)

// ---------------------------------------------------------------------------
// Static scratch (no allocation allowed; referenced directly from kernels).
// ---------------------------------------------------------------------------
__device__ float g_h1[NMAX * 64];   // x @ W1
__device__ float g_o1[NMAX * 64];   // relu(aggregate layer1) = input to GEMM2
__device__ float g_h2[NMAX * 32];   // o1 @ W2
__device__ float g_as1[NMAX], g_ad1[NMAX];
__device__ float g_as2[NMAX], g_ad2[NMAX];
__device__ int   g_deg[NMAX];
__device__ int   g_off[NMAX + 1];
__device__ int   g_cur[NMAX];
__device__ int   g_csr[ETOT];       // src ids grouped by dst
__device__ int   g_bsum[NBMAX];

// ---------------------------------------------------------------------------
// CSR build: deg init (self-loop = 1), histogram, 3-phase exclusive scan,
// scatter of src ids grouped by dst.
// edges_index is INT32 on-device (harness coerces int64 inputs to int32).
// ---------------------------------------------------------------------------
__global__ void init_deg_kernel(int n) {
    int i = blockIdx.x * blockDim.x + threadIdx.x;
    if (i < n) g_deg[i] = 1;   // self-loop
}

__global__ void hist_kernel(const int* __restrict__ ei, int e, int n) {
    int t = blockIdx.x * blockDim.x + threadIdx.x;
    if (t < e) {
        int src = ei[t];
        int dst = ei[e + t];
        // Validity clamp (kept consistent with scatter_kernel so CSR stays
        // well-formed even if an index were out of range).
        if ((unsigned)dst < (unsigned)n && (unsigned)src < (unsigned)n)
            atomicAdd(&g_deg[dst], 1);
    }
}

__global__ void scan_partial_kernel(int n) {
    __shared__ int sm[256];
    int base = blockIdx.x * SCAN_CHUNK;
    int s = 0;
#pragma unroll
    for (int u = 0; u < 4; ++u) {
        int i = base + u * 256 + threadIdx.x;
        if (i < n) s += g_deg[i];
    }
    sm[threadIdx.x] = s;
    __syncthreads();
    for (int st = 128; st > 0; st >>= 1) {
        if (threadIdx.x < st) sm[threadIdx.x] += sm[threadIdx.x + st];
        __syncthreads();
    }
    if (threadIdx.x == 0) g_bsum[blockIdx.x] = sm[0];
}

__global__ void scan_bsum_kernel(int nb, int n) {
    __shared__ int sm[256];
    int t = threadIdx.x;
    int v = (t < nb) ? g_bsum[t] : 0;
    sm[t] = v;
    __syncthreads();
    int total = 0;
    for (int st = 1; st < 256; st <<= 1) {
        int a = 0;
        if (t >= st) a = sm[t - st];
        __syncthreads();
        sm[t] += a;
        __syncthreads();
    }
    if (t < nb) g_bsum[t] = sm[t] - v;   // exclusive
    total = sm[255];
    if (t == 0) g_off[n] = total;        // = sum of all degrees
}

__global__ void scan_final_kernel(int n) {
    __shared__ int sm[256];
    int base = blockIdx.x * SCAN_CHUNK;
    int i0 = base + threadIdx.x * 4;
    int v[4];
    int s = 0;
#pragma unroll
    for (int u = 0; u < 4; ++u) {
        int i = i0 + u;
        v[u] = (i < n) ? g_deg[i] : 0;
        s += v[u];
    }
    sm[threadIdx.x] = s;
    __syncthreads();
    for (int st = 1; st < 256; st <<= 1) {
        int a = 0;
        if (threadIdx.x >= st) a = sm[threadIdx.x - st];
        __syncthreads();
        sm[threadIdx.x] += a;
        __syncthreads();
    }
    int pref = g_bsum[blockIdx.x] + (sm[threadIdx.x] - s);   // exclusive prefix
#pragma unroll
    for (int u = 0; u < 4; ++u) {
        int i = i0 + u;
        if (i < n) { g_off[i] = pref; g_cur[i] = pref; }
        pref += v[u];
    }
}

__global__ void scatter_kernel(const int* __restrict__ ei, int e, int n) {
    int t = blockIdx.x * blockDim.x + threadIdx.x;
    if (t < e) {
        int src = ei[t];
        int dst = ei[e + t];
        if ((unsigned)dst < (unsigned)n && (unsigned)src < (unsigned)n) {
            int pos = atomicAdd(&g_cur[dst], 1);
            g_csr[pos] = src;
        }
    } else if (t < e + n) {
        int i = t - e;
        int pos = atomicAdd(&g_cur[i], 1);
        g_csr[pos] = i;   // self-loop
    }
}

// ---------------------------------------------------------------------------
// Dense GEMM body: H[n, M] = X[n, K] @ W[K, M].  Block = 64 nodes x M cols,
// 256 threads, register tile 4 x (M/16), K staged in 64-wide smem chunks.
// ---------------------------------------------------------------------------
template <int K, int M>
__device__ __forceinline__ void gemm_body(
    const float* __restrict__ X, const float* __restrict__ W,
    float* __restrict__ H, int n)
{
    constexpr int KC = 64;
    constexpr int XS = KC + 4;        // 68: conflict-free row stride
    constexpr int TM = M / 16;        // 4 (M=64) or 2 (M=32)
    __shared__ float xs[64 * XS];
    __shared__ float ws[KC * M];

    const int tid = threadIdx.x;
    const int tx = tid & 15;          // output-column group
    const int ty = tid >> 4;          // node group (0..15)
    const int nb = blockIdx.x * 64;

    float acc[4][TM];
#pragma unroll
    for (int u = 0; u < 4; ++u)
#pragma unroll
        for (int v2 = 0; v2 < TM; ++v2) acc[u][v2] = 0.f;

    for (int kc = 0; kc < K; kc += KC) {
        // X tile: 64 x KC
#pragma unroll
        for (int it = 0; it < (64 * KC / 4) / 256; ++it) {
            int idx = tid + it * 256;
            int r = idx / (KC / 4);
            int c4 = idx % (KC / 4);
            float4 v;
            int node = nb + r;
            if (node < n)
                v = *reinterpret_cast<const float4*>(X + (size_t)node * K + kc + c4 * 4);
            else
                v = make_float4(0.f, 0.f, 0.f, 0.f);
            *reinterpret_cast<float4*>(&xs[r * XS + c4 * 4]) = v;
        }
        // W tile: KC x M (row-major [k][j])
#pragma unroll
        for (int it = 0; it < (KC * M / 4) / 256; ++it) {
            int idx = tid + it * 256;
            int r = idx / (M / 4);
            int c4 = idx % (M / 4);
            *reinterpret_cast<float4*>(&ws[r * M + c4 * 4]) =
                *reinterpret_cast<const float4*>(W + (size_t)(kc + r) * M + c4 * 4);
        }
        __syncthreads();
#pragma unroll 8
        for (int k = 0; k < KC; ++k) {
            float xv[4];
#pragma unroll
            for (int u = 0; u < 4; ++u) xv[u] = xs[(ty * 4 + u) * XS + k];
            float wv[TM];
#pragma unroll
            for (int v2 = 0; v2 < TM; ++v2) wv[v2] = ws[k * M + tx * TM + v2];
#pragma unroll
            for (int u = 0; u < 4; ++u)
#pragma unroll
                for (int v2 = 0; v2 < TM; ++v2)
                    acc[u][v2] = fmaf(xv[u], wv[v2], acc[u][v2]);
        }
        __syncthreads();
    }
#pragma unroll
    for (int u = 0; u < 4; ++u) {
        int node = nb + ty * 4 + u;
        if (node < n) {
#pragma unroll
            for (int v2 = 0; v2 < TM; ++v2)
                H[(size_t)node * M + tx * TM + v2] = acc[u][v2];
        }
    }
}

__global__ void __launch_bounds__(256) gemm1_kernel(
    const float* __restrict__ X, const float* __restrict__ W, int n) {
    gemm_body<128, 64>(X, W, g_h1, n);
}

__global__ void __launch_bounds__(256) gemm2_kernel(
    const float* __restrict__ W, int n) {
    gemm_body<64, 32>(g_o1, W, g_h2, n);
}

// ---------------------------------------------------------------------------
// Per-node attention logits: as[i] = h[i].a_src, ad[i] = h[i].a_dst
// One warp per node.
// ---------------------------------------------------------------------------
__global__ void alpha1_kernel(const float* __restrict__ a_s,
                              const float* __restrict__ a_d, int n)
{
    int w = (blockIdx.x * blockDim.x + threadIdx.x) >> 5;
    int lane = threadIdx.x & 31;
    if (w >= n) return;
    float2 hv = *reinterpret_cast<const float2*>(g_h1 + (size_t)w * 64 + lane * 2);
    float2 av = *reinterpret_cast<const float2*>(a_s + lane * 2);
    float2 dv = *reinterpret_cast<const float2*>(a_d + lane * 2);
    float s = hv.x * av.x + hv.y * av.y;
    float d = hv.x * dv.x + hv.y * dv.y;
#pragma unroll
    for (int o = 16; o; o >>= 1) {
        s += __shfl_xor_sync(0xffffffffu, s, o);
        d += __shfl_xor_sync(0xffffffffu, d, o);
    }
    if (lane == 0) { g_as1[w] = s; g_ad1[w] = d; }
}

__global__ void alpha2_kernel(const float* __restrict__ a_s,
                              const float* __restrict__ a_d, int n)
{
    int w = (blockIdx.x * blockDim.x + threadIdx.x) >> 5;
    int lane = threadIdx.x & 31;
    if (w >= n) return;
    float hv = g_h2[(size_t)w * 32 + lane];
    float s = hv * a_s[lane];
    float d = hv * a_d[lane];
#pragma unroll
    for (int o = 16; o; o >>= 1) {
        s += __shfl_xor_sync(0xffffffffu, s, o);
        d += __shfl_xor_sync(0xffffffffu, d, o);
    }
    if (lane == 0) { g_as2[w] = s; g_ad2[w] = d; }
}

// ---------------------------------------------------------------------------
// Gather layer 1: warp per destination node. D=64, lane owns 2 floats.
// out = relu( (sum_e w_e * h[src_e]) / (sum_e w_e + 1e-16) + b )
// Segment-max skipped: softmax is shift-invariant and logits are O(1), so
// exp() cannot overflow fp32 here.
// ---------------------------------------------------------------------------
__global__ void __launch_bounds__(256) gather64_kernel(
    const float* __restrict__ b, int n)
{
    int node = (blockIdx.x * blockDim.x + threadIdx.x) >> 5;
    int lane = threadIdx.x & 31;
    if (node >= n) return;
    int p0 = g_off[node], p1 = g_off[node + 1];
    float adv = g_ad1[node];
    float sum = 0.f, a0 = 0.f, a1 = 0.f;
    for (int p = p0; p < p1; ++p) {
        int src = g_csr[p];
        float ev = g_as1[src] + adv;
        ev = ev > 0.f ? ev : 0.2f * ev;
        float w = __expf(ev);
        float2 hv = *reinterpret_cast<const float2*>(g_h1 + (size_t)src * 64 + lane * 2);
        sum += w;
        a0 = fmaf(w, hv.x, a0);
        a1 = fmaf(w, hv.y, a1);
    }
    float inv = 1.f / (sum + 1e-16f);
    float2 o;
    o.x = fmaxf(fmaf(a0, inv, b[lane * 2]), 0.f);
    o.y = fmaxf(fmaf(a1, inv, b[lane * 2 + 1]), 0.f);
    *reinterpret_cast<float2*>(g_o1 + (size_t)node * 64 + lane * 2) = o;
}

// ---------------------------------------------------------------------------
// Gather layer 2 + fused log_softmax: warp per destination, lane = channel.
// ---------------------------------------------------------------------------
__global__ void __launch_bounds__(256) gather32_kernel(
    const float* __restrict__ b, float* __restrict__ out, int n)
{
    int node = (blockIdx.x * blockDim.x + threadIdx.x) >> 5;
    int lane = threadIdx.x & 31;
    if (node >= n) return;
    int p0 = g_off[node], p1 = g_off[node + 1];
    float adv = g_ad2[node];
    float sum = 0.f, acc = 0.f;
    for (int p = p0; p < p1; ++p) {
        int src = g_csr[p];
        float ev = g_as2[src] + adv;
        ev = ev > 0.f ? ev : 0.2f * ev;
        float w = __expf(ev);
        float hv = g_h2[(size_t)src * 32 + lane];
        sum += w;
        acc = fmaf(w, hv, acc);
    }
    float v = fmaf(acc, 1.f / (sum + 1e-16f), b[lane]);
    // log_softmax across the 32 lanes
    float m = v;
#pragma unroll
    for (int o = 16; o; o >>= 1) m = fmaxf(m, __shfl_xor_sync(0xffffffffu, m, o));
    float ex = __expf(v - m);
    float s2 = ex;
#pragma unroll
    for (int o = 16; o; o >>= 1) s2 += __shfl_xor_sync(0xffffffffu, s2, o);
    out[(size_t)node * 32 + lane] = v - m - __logf(s2);
}

// ---------------------------------------------------------------------------
// Launch: kernel launches only — no runtime API calls of any kind.
// ---------------------------------------------------------------------------
extern "C" void kernel_launch(void* const* d_in, const int* in_sizes, int n_in,
                              void* d_out, int out_size) {
    const float* x   = (const float*)d_in[0];
    const int*   ei  = (const int*)d_in[1];     // int64 in reference, coerced to int32 by harness
    const float* W1  = (const float*)d_in[2];
    const float* aS1 = (const float*)d_in[3];
    const float* aD1 = (const float*)d_in[4];
    const float* b1  = (const float*)d_in[5];
    const float* W2  = (const float*)d_in[6];
    const float* aS2 = (const float*)d_in[7];
    const float* aD2 = (const float*)d_in[8];
    const float* b2  = (const float*)d_in[9];
    float* out = (float*)d_out;

    const int n = in_sizes[0] / 128;
    const int e = in_sizes[1] / 2;
    const int etot = e + n;
    const int nb = (n + SCAN_CHUNK - 1) / SCAN_CHUNK;

    // CSR build (shared by both layers)
    init_deg_kernel<<<(n + 255) / 256, 256>>>(n);
    hist_kernel<<<(e + 255) / 256, 256>>>(ei, e, n);
    scan_partial_kernel<<<nb, 256>>>(n);
    scan_bsum_kernel<<<1, 256>>>(nb, n);
    scan_final_kernel<<<nb, 256>>>(n);
    scatter_kernel<<<(etot + 255) / 256, 256>>>(ei, e, n);

    // Layer 1
    gemm1_kernel<<<(n + 63) / 64, 256>>>(x, W1, n);
    alpha1_kernel<<<(n * 32 + 255) / 256, 256>>>(aS1, aD1, n);
    gather64_kernel<<<(n * 32 + 255) / 256, 256>>>(b1, n);

    // Layer 2 (+ fused log_softmax)
    gemm2_kernel<<<(n + 63) / 64, 256>>>(W2, n);
    alpha2_kernel<<<(n * 32 + 255) / 256, 256>>>(aS2, aD2, n);
    gather32_kernel<<<(n * 32 + 255) / 256, 256>>>(b2, out, n);
}

// round 4
// speedup vs baseline: 1.1108x; 1.1108x over previous
#include <cuda_runtime.h>
#include <cstdint>

#define NMAX 100000
#define EMAX 1600000
#define ETOT (EMAX + NMAX)
#define SCAN_CHUNK 1024
#define NBMAX ((NMAX + SCAN_CHUNK - 1) / SCAN_CHUNK)
#define HIST_BLOCKS 1184   // 8 * 148 SMs, grid-stride over edges

// ---------------------------------------------------------------------------
// Static scratch
// ---------------------------------------------------------------------------
__device__ float g_h1[NMAX * 64];   // x @ W1
__device__ float g_o1[NMAX * 64];   // relu(aggregate layer1) = input to GEMM2
__device__ float g_h2[NMAX * 32];   // o1 @ W2
__device__ float g_as1[NMAX], g_ad1[NMAX];
__device__ float g_as2[NMAX], g_ad2[NMAX];
__device__ int   g_deg[NMAX];
__device__ int   g_off[NMAX + 1];
__device__ int   g_cur[NMAX];
__device__ int   g_csr[ETOT];       // src ids grouped by dst
__device__ int   g_bsum[NBMAX];

// ---------------------------------------------------------------------------
// CSR build pieces
// ---------------------------------------------------------------------------
__global__ void init_deg_kernel(int n) {
    int i = blockIdx.x * blockDim.x + threadIdx.x;
    if (i < n) g_deg[i] = 1;   // self-loop
}

__global__ void scan_partial_kernel(int n) {
    __shared__ int sm[256];
    int base = blockIdx.x * SCAN_CHUNK;
    int s = 0;
#pragma unroll
    for (int u = 0; u < 4; ++u) {
        int i = base + u * 256 + threadIdx.x;
        if (i < n) s += g_deg[i];
    }
    sm[threadIdx.x] = s;
    __syncthreads();
    for (int st = 128; st > 0; st >>= 1) {
        if (threadIdx.x < st) sm[threadIdx.x] += sm[threadIdx.x + st];
        __syncthreads();
    }
    if (threadIdx.x == 0) g_bsum[blockIdx.x] = sm[0];
}

__global__ void scan_bsum_kernel(int nb, int n) {
    __shared__ int sm[256];
    int t = threadIdx.x;
    int v = (t < nb) ? g_bsum[t] : 0;
    sm[t] = v;
    __syncthreads();
    for (int st = 1; st < 256; st <<= 1) {
        int a = 0;
        if (t >= st) a = sm[t - st];
        __syncthreads();
        sm[t] += a;
        __syncthreads();
    }
    if (t < nb) g_bsum[t] = sm[t] - v;   // exclusive
    if (t == 0) g_off[n] = sm[255];      // total degree
}

__global__ void scan_final_kernel(int n) {
    __shared__ int sm[256];
    int base = blockIdx.x * SCAN_CHUNK;
    int i0 = base + threadIdx.x * 4;
    int v[4];
    int s = 0;
#pragma unroll
    for (int u = 0; u < 4; ++u) {
        int i = i0 + u;
        v[u] = (i < n) ? g_deg[i] : 0;
        s += v[u];
    }
    sm[threadIdx.x] = s;
    __syncthreads();
    for (int st = 1; st < 256; st <<= 1) {
        int a = 0;
        if (threadIdx.x >= st) a = sm[threadIdx.x - st];
        __syncthreads();
        sm[threadIdx.x] += a;
        __syncthreads();
    }
    int pref = g_bsum[blockIdx.x] + (sm[threadIdx.x] - s);
#pragma unroll
    for (int u = 0; u < 4; ++u) {
        int i = i0 + u;
        if (i < n) { g_off[i] = pref; g_cur[i] = pref; }
        pref += v[u];
    }
}

__global__ void scatter_kernel(const int* __restrict__ ei, int e, int n) {
    int t = blockIdx.x * blockDim.x + threadIdx.x;
    if (t < e) {
        int src = ei[t];
        int dst = ei[e + t];
        int pos = atomicAdd(&g_cur[dst], 1);
        g_csr[pos] = src;
    } else if (t < e + n) {
        int i = t - e;
        int pos = atomicAdd(&g_cur[i], 1);
        g_csr[pos] = i;   // self-loop
    }
}

// ---------------------------------------------------------------------------
// GEMM body with fused alpha epilogue.
// H[n, M] = X[n, K] @ W[K, M]; as[i] = H[i]·a_s ; ad[i] = H[i]·a_d.
// Block = 64 nodes x M cols, 256 threads, register tile 4 x (M/16).
// Thread layout: tx = tid&15 (column group), ty = tid>>4 (node group).
// Alpha reduction: shfl over the 16 tx lanes (lane bits 0..3).
// ---------------------------------------------------------------------------
template <int K, int M>
__device__ __forceinline__ void gemm_alpha_body(
    const float* __restrict__ X, const float* __restrict__ W,
    float* __restrict__ H,
    const float* __restrict__ a_s, const float* __restrict__ a_d,
    float* __restrict__ as_out, float* __restrict__ ad_out,
    int n, int bid)
{
    constexpr int KC = 64;
    constexpr int XS = KC + 4;        // conflict-free row stride
    constexpr int TM = M / 16;        // 4 (M=64) or 2 (M=32)
    __shared__ float xs[64 * XS];
    __shared__ float ws[KC * M];

    const int tid = threadIdx.x;
    const int tx = tid & 15;
    const int ty = tid >> 4;
    const int nb = bid * 64;

    float acc[4][TM];
#pragma unroll
    for (int u = 0; u < 4; ++u)
#pragma unroll
        for (int v2 = 0; v2 < TM; ++v2) acc[u][v2] = 0.f;

    for (int kc = 0; kc < K; kc += KC) {
#pragma unroll
        for (int it = 0; it < (64 * KC / 4) / 256; ++it) {
            int idx = tid + it * 256;
            int r = idx / (KC / 4);
            int c4 = idx % (KC / 4);
            float4 v;
            int node = nb + r;
            if (node < n)
                v = *reinterpret_cast<const float4*>(X + (size_t)node * K + kc + c4 * 4);
            else
                v = make_float4(0.f, 0.f, 0.f, 0.f);
            *reinterpret_cast<float4*>(&xs[r * XS + c4 * 4]) = v;
        }
#pragma unroll
        for (int it = 0; it < (KC * M / 4) / 256; ++it) {
            int idx = tid + it * 256;
            int r = idx / (M / 4);
            int c4 = idx % (M / 4);
            *reinterpret_cast<float4*>(&ws[r * M + c4 * 4]) =
                *reinterpret_cast<const float4*>(W + (size_t)(kc + r) * M + c4 * 4);
        }
        __syncthreads();
#pragma unroll 8
        for (int k = 0; k < KC; ++k) {
            float xv[4];
#pragma unroll
            for (int u = 0; u < 4; ++u) xv[u] = xs[(ty * 4 + u) * XS + k];
            float wv[TM];
#pragma unroll
            for (int v2 = 0; v2 < TM; ++v2) wv[v2] = ws[k * M + tx * TM + v2];
#pragma unroll
            for (int u = 0; u < 4; ++u)
#pragma unroll
                for (int v2 = 0; v2 < TM; ++v2)
                    acc[u][v2] = fmaf(xv[u], wv[v2], acc[u][v2]);
        }
        __syncthreads();
    }

    // Epilogue: store H, accumulate alpha partials, reduce over tx.
    float asv[TM], adv[TM];
#pragma unroll
    for (int v2 = 0; v2 < TM; ++v2) {
        asv[v2] = a_s[tx * TM + v2];
        adv[v2] = a_d[tx * TM + v2];
    }
#pragma unroll
    for (int u = 0; u < 4; ++u) {
        int node = nb + ty * 4 + u;
        float s = 0.f, d = 0.f;
#pragma unroll
        for (int v2 = 0; v2 < TM; ++v2) {
            float val = acc[u][v2];
            s = fmaf(val, asv[v2], s);
            d = fmaf(val, adv[v2], d);
        }
#pragma unroll
        for (int o = 8; o; o >>= 1) {
            s += __shfl_xor_sync(0xffffffffu, s, o);
            d += __shfl_xor_sync(0xffffffffu, d, o);
        }
        if (node < n) {
#pragma unroll
            for (int v2 = 0; v2 < TM; ++v2)
                H[(size_t)node * M + tx * TM + v2] = acc[u][v2];
            if (tx == 0) { as_out[node] = s; ad_out[node] = d; }
        }
    }
}

// Fused: GEMM1 (+alpha1) blocks, then histogram blocks (independent work).
__global__ void __launch_bounds__(256) fused_gemm1_hist_kernel(
    const float* __restrict__ X, const float* __restrict__ W1,
    const float* __restrict__ aS1, const float* __restrict__ aD1,
    const int* __restrict__ ei, int n, int e, int gemm_blocks)
{
    if ((int)blockIdx.x < gemm_blocks) {
        gemm_alpha_body<128, 64>(X, W1, g_h1, aS1, aD1, g_as1, g_ad1, n, blockIdx.x);
    } else {
        int hb = gridDim.x - gemm_blocks;
        for (int t = (blockIdx.x - gemm_blocks) * 256 + threadIdx.x; t < e;
             t += hb * 256) {
            int dst = ei[e + t];
            atomicAdd(&g_deg[dst], 1);
        }
    }
}

__global__ void __launch_bounds__(256) gemm2_kernel(
    const float* __restrict__ W2,
    const float* __restrict__ aS2, const float* __restrict__ aD2, int n)
{
    gemm_alpha_body<64, 32>(g_o1, W2, g_h2, aS2, aD2, g_as2, g_ad2, n, blockIdx.x);
}

// ---------------------------------------------------------------------------
// Gather layer 1: warp per destination node. D=64, lane owns 2 floats.
// out = relu( (sum_e w_e * h[src_e]) / (sum_e w_e + 1e-16) + b )
// Softmax shift dropped (shift-invariant; logits O(1), no overflow risk).
// Unroll 4 for memory-level parallelism on the csr->h dependent chain.
// ---------------------------------------------------------------------------
__global__ void __launch_bounds__(256) gather64_kernel(
    const float* __restrict__ b, int n)
{
    int node = (blockIdx.x * blockDim.x + threadIdx.x) >> 5;
    int lane = threadIdx.x & 31;
    if (node >= n) return;
    int p0 = g_off[node], p1 = g_off[node + 1];
    float advl = g_ad1[node];
    float sum = 0.f, a0 = 0.f, a1 = 0.f;
#pragma unroll 4
    for (int p = p0; p < p1; ++p) {
        int src = g_csr[p];
        float ev = g_as1[src] + advl;
        ev = ev > 0.f ? ev : 0.2f * ev;
        float w = __expf(ev);
        float2 hv = *reinterpret_cast<const float2*>(g_h1 + (size_t)src * 64 + lane * 2);
        sum += w;
        a0 = fmaf(w, hv.x, a0);
        a1 = fmaf(w, hv.y, a1);
    }
    float inv = 1.f / (sum + 1e-16f);
    float2 o;
    o.x = fmaxf(fmaf(a0, inv, b[lane * 2]), 0.f);
    o.y = fmaxf(fmaf(a1, inv, b[lane * 2 + 1]), 0.f);
    *reinterpret_cast<float2*>(g_o1 + (size_t)node * 64 + lane * 2) = o;
}

// ---------------------------------------------------------------------------
// Gather layer 2 + fused log_softmax: warp per destination, lane = channel.
// ---------------------------------------------------------------------------
__global__ void __launch_bounds__(256) gather32_kernel(
    const float* __restrict__ b, float* __restrict__ out, int n)
{
    int node = (blockIdx.x * blockDim.x + threadIdx.x) >> 5;
    int lane = threadIdx.x & 31;
    if (node >= n) return;
    int p0 = g_off[node], p1 = g_off[node + 1];
    float advl = g_ad2[node];
    float sum = 0.f, acc = 0.f;
#pragma unroll 4
    for (int p = p0; p < p1; ++p) {
        int src = g_csr[p];
        float ev = g_as2[src] + advl;
        ev = ev > 0.f ? ev : 0.2f * ev;
        float w = __expf(ev);
        float hv = g_h2[(size_t)src * 32 + lane];
        sum += w;
        acc = fmaf(w, hv, acc);
    }
    float v = fmaf(acc, 1.f / (sum + 1e-16f), b[lane]);
    float m = v;
#pragma unroll
    for (int o = 16; o; o >>= 1) m = fmaxf(m, __shfl_xor_sync(0xffffffffu, m, o));
    float ex = __expf(v - m);
    float s2 = ex;
#pragma unroll
    for (int o = 16; o; o >>= 1) s2 += __shfl_xor_sync(0xffffffffu, s2, o);
    out[(size_t)node * 32 + lane] = v - m - __logf(s2);
}

// ---------------------------------------------------------------------------
// Launch: kernel launches only.
// ---------------------------------------------------------------------------
extern "C" void kernel_launch(void* const* d_in, const int* in_sizes, int n_in,
                              void* d_out, int out_size) {
    const float* x   = (const float*)d_in[0];
    const int*   ei  = (const int*)d_in[1];     // int64 coerced to int32 by harness
    const float* W1  = (const float*)d_in[2];
    const float* aS1 = (const float*)d_in[3];
    const float* aD1 = (const float*)d_in[4];
    const float* b1  = (const float*)d_in[5];
    const float* W2  = (const float*)d_in[6];
    const float* aS2 = (const float*)d_in[7];
    const float* aD2 = (const float*)d_in[8];
    const float* b2  = (const float*)d_in[9];
    float* out = (float*)d_out;

    const int n = in_sizes[0] / 128;
    const int e = in_sizes[1] / 2;
    const int etot = e + n;
    const int nb = (n + SCAN_CHUNK - 1) / SCAN_CHUNK;
    const int gemm1_blocks = (n + 63) / 64;

    // deg init, then fused [GEMM1+alpha1 | histogram]
    init_deg_kernel<<<(n + 255) / 256, 256>>>(n);
    fused_gemm1_hist_kernel<<<gemm1_blocks + HIST_BLOCKS, 256>>>(
        x, W1, aS1, aD1, ei, n, e, gemm1_blocks);

    // CSR offsets + scatter
    scan_partial_kernel<<<nb, 256>>>(n);
    scan_bsum_kernel<<<1, 256>>>(nb, n);
    scan_final_kernel<<<nb, 256>>>(n);
    scatter_kernel<<<(etot + 255) / 256, 256>>>(ei, e, n);

    // Layer 1 aggregate (+bias+ReLU)
    gather64_kernel<<<(n * 32 + 255) / 256, 256>>>(b1, n);

    // Layer 2
    gemm2_kernel<<<(n + 63) / 64, 256>>>(W2, aS2, aD2, n);
    gather32_kernel<<<(n * 32 + 255) / 256, 256>>>(b2, out, n);
}